// round 1
// baseline (speedup 1.0000x reference)
#include <cuda_runtime.h>
#include <math.h>

#define BATCH 4
#define CIN   256
#define DD    64
#define HW    4096
#define NPIX  4096

// scratch (no cudaMalloc allowed)
__device__ float g_att[BATCH*DD*HW];   // in-projection output
__device__ float g_q[BATCH*DD*HW];
__device__ float g_k[BATCH*DD*HW];
__device__ float g_v[BATCH*DD*HW];
__device__ float g_ao[BATCH*DD*HW];    // attention output

// ---------------------------------------------------------------------------
// 1x1 in-projection: att[b,d,p] = sum_c w[d,c] * x[b,c,p] + bias[d]
// grid (64, B), block 256. tp = pixel-in-tile(64), tg = d-group(4 x 16)
// ---------------------------------------------------------------------------
__global__ __launch_bounds__(256) void k_inproj(const float* __restrict__ x,
                                                const float* __restrict__ w,
                                                const float* __restrict__ bias) {
    int b  = blockIdx.y;
    int p0 = blockIdx.x * 64;
    int tid = threadIdx.x;
    int tp = tid & 63, tg = tid >> 6;
    __shared__ float xs[32][65];
    __shared__ float ws[64][33];
    float acc[16];
#pragma unroll
    for (int i = 0; i < 16; i++) acc[i] = 0.f;

    for (int c0 = 0; c0 < CIN; c0 += 32) {
        __syncthreads();
#pragma unroll
        for (int r = 0; r < 8; r++) {
            int lin = tid + r * 256;
            int cc = lin >> 6, pp = lin & 63;
            xs[cc][pp] = x[(size_t)(b*CIN + c0 + cc)*HW + p0 + pp];
        }
#pragma unroll
        for (int r = 0; r < 8; r++) {
            int lin = tid + r * 256;
            int dd = lin >> 5, cc = lin & 31;
            ws[dd][cc] = w[dd*CIN + c0 + cc];
        }
        __syncthreads();
#pragma unroll 8
        for (int cc = 0; cc < 32; cc++) {
            float xv = xs[cc][tp];
#pragma unroll
            for (int dd = 0; dd < 16; dd++)
                acc[dd] += ws[tg*16 + dd][cc] * xv;
        }
    }
#pragma unroll
    for (int dd = 0; dd < 16; dd++) {
        int d = tg*16 + dd;
        g_att[(size_t)(b*DD + d)*HW + p0 + tp] = acc[dd] + bias[d];
    }
}

// ---------------------------------------------------------------------------
// 3x3 conv (pad 1), D=64 -> D=64. One kernel does q/k/v via blockIdx.z.
// grid (4, 4, B*3). block 256. 16x16 spatial tile, each thread: 2x2 pixels x 16 oc.
// dynamic smem: patch[16][18][18] + ws[64][16][9]
// ---------------------------------------------------------------------------
#define ICCH 16
#define CONV_SMEM ((ICCH*324 + 64*ICCH*9) * 4)

__global__ __launch_bounds__(256) void k_conv3x3(const float* __restrict__ wq, const float* __restrict__ bq,
                                                 const float* __restrict__ wk, const float* __restrict__ bk,
                                                 const float* __restrict__ wv, const float* __restrict__ bv) {
    extern __shared__ float sm[];
    float* patch = sm;                  // [ICCH][18][18]
    float* ws    = sm + ICCH*324;       // [64][ICCH][9]

    int b     = blockIdx.z / 3;
    int which = blockIdx.z % 3;
    const float* w    = (which == 0) ? wq : (which == 1) ? wk : wv;
    const float* bias = (which == 0) ? bq : (which == 1) ? bk : bv;
    float* out        = (which == 0) ? g_q : (which == 1) ? g_k : g_v;

    int ty0 = blockIdx.y * 16, tx0 = blockIdx.x * 16;
    int tid = threadIdx.x;
    int tq = tid & 63, tg = tid >> 6;
    int qx = tq & 7, qy = tq >> 3;

    float acc[4][16];
#pragma unroll
    for (int p = 0; p < 4; p++)
#pragma unroll
        for (int o = 0; o < 16; o++) acc[p][o] = 0.f;

    for (int c0 = 0; c0 < DD; c0 += ICCH) {
        __syncthreads();
        // load halo patch (zero padded)
        for (int r = 0; r < 21; r++) {
            int lin = tid + r * 256;
            if (lin < ICCH*324) {
                int ic = lin / 324, rem = lin % 324;
                int py = rem / 18, px = rem % 18;
                int gy = ty0 + py - 1, gx = tx0 + px - 1;
                float v = 0.f;
                if (gy >= 0 && gy < 64 && gx >= 0 && gx < 64)
                    v = g_att[(size_t)(b*DD + c0 + ic)*HW + gy*64 + gx];
                patch[lin] = v;
            }
        }
        // load weights chunk: ws[oc][ic][tap]
        for (int r = 0; r < 36; r++) {
            int lin = tid + r * 256;
            int oc = lin / 144, rem = lin % 144;
            int ic = rem / 9, tap = rem % 9;
            ws[lin] = w[oc*576 + (c0 + ic)*9 + tap];
        }
        __syncthreads();

#pragma unroll 1
        for (int ic = 0; ic < ICCH; ic++) {
            float in44[4][4];
#pragma unroll
            for (int iy = 0; iy < 4; iy++)
#pragma unroll
                for (int ix = 0; ix < 4; ix++)
                    in44[iy][ix] = patch[ic*324 + (qy*2 + iy)*18 + qx*2 + ix];
#pragma unroll
            for (int o = 0; o < 16; o++) {
                const float* wp = ws + (tg*16 + o)*144 + ic*9;
                float w0 = wp[0], w1 = wp[1], w2 = wp[2];
                float w3 = wp[3], w4 = wp[4], w5 = wp[5];
                float w6 = wp[6], w7 = wp[7], w8 = wp[8];
#pragma unroll
                for (int dy = 0; dy < 2; dy++)
#pragma unroll
                    for (int dx = 0; dx < 2; dx++) {
                        acc[dy*2 + dx][o] +=
                              w0*in44[dy  ][dx] + w1*in44[dy  ][dx+1] + w2*in44[dy  ][dx+2]
                            + w3*in44[dy+1][dx] + w4*in44[dy+1][dx+1] + w5*in44[dy+1][dx+2]
                            + w6*in44[dy+2][dx] + w7*in44[dy+2][dx+1] + w8*in44[dy+2][dx+2];
                    }
            }
        }
    }
#pragma unroll
    for (int o = 0; o < 16; o++) {
        int oc = tg*16 + o;
        float bb = bias[oc];
#pragma unroll
        for (int dy = 0; dy < 2; dy++)
#pragma unroll
            for (int dx = 0; dx < 2; dx++)
                out[(size_t)(b*DD + oc)*HW + (ty0 + qy*2 + dy)*64 + tx0 + qx*2 + dx] =
                    acc[dy*2 + dx][o] + bb;
    }
}

// ---------------------------------------------------------------------------
// Flash attention, fp32. energy[i,j] = sum_c Q[c,i]K[c,j]; softmax over j;
// out[c,i] = sum_j V[c,j] P[i,j]. Bq = Bk = 64, d = 64.
// grid (64, B), block 256. thread (ti,tj): tj = tid&15, ti = tid>>4.
//   S phase: rows i = ti*4.., cols j = tj*4.. (4x4 micro-tile)
//   PV phase: rows i = ti*4.., channels c = tj*4.. (same rows => softmax state local)
// smem: Qs,Ks,Vs,Ps each [64][68] floats (row stride 68 keeps float4 alignment)
// ---------------------------------------------------------------------------
#define ATTN_SMEM (4 * 64 * 68 * 4)

__global__ __launch_bounds__(256) void k_attn() {
    extern __shared__ float sm[];
    float* Qs = sm;
    float* Ks = sm + 64*68;
    float* Vs = sm + 2*64*68;
    float* Ps = sm + 3*64*68;

    int b  = blockIdx.y;
    int i0 = blockIdx.x * 64;
    int tid = threadIdx.x;
    int tj = tid & 15, ti = tid >> 4;
    int ti4 = ti * 4, tj4 = tj * 4;

    const float* Qg = g_q + (size_t)b*DD*NPIX;
    const float* Kg = g_k + (size_t)b*DD*NPIX;
    const float* Vg = g_v + (size_t)b*DD*NPIX;

#pragma unroll
    for (int r = 0; r < 16; r++) {
        int lin = tid + r * 256;
        int c = lin >> 6, ii = lin & 63;
        Qs[c*68 + ii] = Qg[(size_t)c*NPIX + i0 + ii];
    }

    float m[4], l[4], O[4][4];
#pragma unroll
    for (int ii = 0; ii < 4; ii++) {
        m[ii] = -1e30f; l[ii] = 0.f;
#pragma unroll
        for (int cc = 0; cc < 4; cc++) O[ii][cc] = 0.f;
    }

    for (int j0 = 0; j0 < NPIX; j0 += 64) {
        __syncthreads();
#pragma unroll
        for (int r = 0; r < 16; r++) {
            int lin = tid + r * 256;
            int c = lin >> 6, jj = lin & 63;
            float kv = Kg[(size_t)c*NPIX + j0 + jj];
            float vv = Vg[(size_t)c*NPIX + j0 + jj];
            Ks[c*68 + jj] = kv;       // [c][j]
            Vs[jj*68 + c] = vv;       // [j][c] (transposed)
        }
        __syncthreads();

        // S = Q^T K  (4x4 per thread)
        float s[4][4];
#pragma unroll
        for (int ii = 0; ii < 4; ii++)
#pragma unroll
            for (int jj = 0; jj < 4; jj++) s[ii][jj] = 0.f;
#pragma unroll 8
        for (int c = 0; c < 64; c++) {
            float4 q4 = *(const float4*)&Qs[c*68 + ti4];
            float4 k4 = *(const float4*)&Ks[c*68 + tj4];
            s[0][0] += q4.x*k4.x; s[0][1] += q4.x*k4.y; s[0][2] += q4.x*k4.z; s[0][3] += q4.x*k4.w;
            s[1][0] += q4.y*k4.x; s[1][1] += q4.y*k4.y; s[1][2] += q4.y*k4.z; s[1][3] += q4.y*k4.w;
            s[2][0] += q4.z*k4.x; s[2][1] += q4.z*k4.y; s[2][2] += q4.z*k4.z; s[2][3] += q4.z*k4.w;
            s[3][0] += q4.w*k4.x; s[3][1] += q4.w*k4.y; s[3][2] += q4.w*k4.z; s[3][3] += q4.w*k4.w;
        }

        // online softmax per row (row group = 16 lanes)
        float p[4][4];
#pragma unroll
        for (int ii = 0; ii < 4; ii++) {
            float rm = fmaxf(fmaxf(s[ii][0], s[ii][1]), fmaxf(s[ii][2], s[ii][3]));
            rm = fmaxf(rm, __shfl_xor_sync(0xffffffffu, rm, 1));
            rm = fmaxf(rm, __shfl_xor_sync(0xffffffffu, rm, 2));
            rm = fmaxf(rm, __shfl_xor_sync(0xffffffffu, rm, 4));
            rm = fmaxf(rm, __shfl_xor_sync(0xffffffffu, rm, 8));
            float mn = fmaxf(m[ii], rm);
            float sc = __expf(m[ii] - mn);
            m[ii] = mn;
            float rs = 0.f;
#pragma unroll
            for (int jj = 0; jj < 4; jj++) { p[ii][jj] = __expf(s[ii][jj] - mn); rs += p[ii][jj]; }
            rs += __shfl_xor_sync(0xffffffffu, rs, 1);
            rs += __shfl_xor_sync(0xffffffffu, rs, 2);
            rs += __shfl_xor_sync(0xffffffffu, rs, 4);
            rs += __shfl_xor_sync(0xffffffffu, rs, 8);
            l[ii] = l[ii]*sc + rs;
#pragma unroll
            for (int cc = 0; cc < 4; cc++) O[ii][cc] *= sc;
        }

#pragma unroll
        for (int ii = 0; ii < 4; ii++)
            *(float4*)&Ps[(ti4 + ii)*68 + tj4] = make_float4(p[ii][0], p[ii][1], p[ii][2], p[ii][3]);
        __syncthreads();

        // O[i][c] += sum_j P[i][j] * V[j][c]
#pragma unroll 4
        for (int jj0 = 0; jj0 < 64; jj0 += 4) {
            float4 v0 = *(const float4*)&Vs[(jj0 + 0)*68 + tj4];
            float4 v1 = *(const float4*)&Vs[(jj0 + 1)*68 + tj4];
            float4 v2 = *(const float4*)&Vs[(jj0 + 2)*68 + tj4];
            float4 v3 = *(const float4*)&Vs[(jj0 + 3)*68 + tj4];
#pragma unroll
            for (int ii = 0; ii < 4; ii++) {
                float4 pr = *(const float4*)&Ps[(ti4 + ii)*68 + jj0];
                O[ii][0] += pr.x*v0.x + pr.y*v1.x + pr.z*v2.x + pr.w*v3.x;
                O[ii][1] += pr.x*v0.y + pr.y*v1.y + pr.z*v2.y + pr.w*v3.y;
                O[ii][2] += pr.x*v0.z + pr.y*v1.z + pr.z*v2.z + pr.w*v3.z;
                O[ii][3] += pr.x*v0.w + pr.y*v1.w + pr.z*v2.w + pr.w*v3.w;
            }
        }
    }

    __syncthreads();
    // stage normalized output (c-major) into Ks, then write coalesced
#pragma unroll
    for (int ii = 0; ii < 4; ii++) {
        float inv = 1.f / l[ii];
#pragma unroll
        for (int cc = 0; cc < 4; cc++)
            Ks[(tj4 + cc)*68 + ti4 + ii] = O[ii][cc] * inv;
    }
    __syncthreads();
#pragma unroll
    for (int r = 0; r < 16; r++) {
        int lin = tid + r * 256;
        int c = lin >> 6, ii = lin & 63;
        g_ao[(size_t)(b*DD + c)*NPIX + i0 + ii] = Ks[c*68 + ii];
    }
}

// ---------------------------------------------------------------------------
// out-projection (64->256) + residual gamma*x + channel LayerNorm, fused.
// grid (64, B), block 256. tp = pixel(64), tg = co-group(4 x 64 channels).
// Block holds all 256 channels for its 64 pixels -> LN reduction in smem.
// ---------------------------------------------------------------------------
__global__ __launch_bounds__(256) void k_outproj_ln(const float* __restrict__ x,
                                                    const float* __restrict__ w,
                                                    const float* __restrict__ bias,
                                                    const float* __restrict__ gamma,
                                                    const float* __restrict__ lnw,
                                                    const float* __restrict__ lnb,
                                                    float* __restrict__ out) {
    int b  = blockIdx.y;
    int p0 = blockIdx.x * 64;
    int tid = threadIdx.x;
    int tp = tid & 63, tg = tid >> 6;
    __shared__ float xs[16][65];
    __shared__ float ws[256][17];
    __shared__ float red[2][4][64];

    float acc[64];
#pragma unroll
    for (int i = 0; i < 64; i++) acc[i] = 0.f;

    for (int d0 = 0; d0 < DD; d0 += 16) {
        __syncthreads();
#pragma unroll
        for (int r = 0; r < 4; r++) {
            int lin = tid + r * 256;
            int cc = lin >> 6, pp = lin & 63;
            xs[cc][pp] = g_ao[(size_t)(b*DD + d0 + cc)*HW + p0 + pp];
        }
#pragma unroll
        for (int r = 0; r < 16; r++) {
            int lin = tid + r * 256;
            int co = lin >> 4, cc = lin & 15;
            ws[co][cc] = w[co*DD + d0 + cc];
        }
        __syncthreads();
#pragma unroll 4
        for (int cc = 0; cc < 16; cc++) {
            float xv = xs[cc][tp];
#pragma unroll
            for (int oo = 0; oo < 64; oo++)
                acc[oo] += ws[tg*64 + oo][cc] * xv;
        }
    }

    float g = gamma[0];
    float s = 0.f, ss = 0.f;
#pragma unroll
    for (int oo = 0; oo < 64; oo++) {
        int co = tg*64 + oo;
        float v = g * x[(size_t)(b*CIN + co)*HW + p0 + tp] + acc[oo] + bias[co];
        acc[oo] = v;
        s += v; ss += v*v;
    }
    red[0][tg][tp] = s;
    red[1][tg][tp] = ss;
    __syncthreads();
    float st  = red[0][0][tp] + red[0][1][tp] + red[0][2][tp] + red[0][3][tp];
    float sst = red[1][0][tp] + red[1][1][tp] + red[1][2][tp] + red[1][3][tp];
    float mu  = st * (1.f/256.f);
    float var = sst * (1.f/256.f) - mu*mu;
    float rstd = rsqrtf(var + 1e-5f);
#pragma unroll
    for (int oo = 0; oo < 64; oo++) {
        int co = tg*64 + oo;
        out[(size_t)(b*CIN + co)*HW + p0 + tp] = (acc[oo] - mu) * rstd * lnw[co] + lnb[co];
    }
}

// ---------------------------------------------------------------------------
extern "C" void kernel_launch(void* const* d_in, const int* in_sizes, int n_in,
                              void* d_out, int out_size) {
    const float* x     = (const float*)d_in[0];
    const float* w_in  = (const float*)d_in[1];
    const float* b_in  = (const float*)d_in[2];
    const float* wq    = (const float*)d_in[3];
    const float* bq    = (const float*)d_in[4];
    const float* wk    = (const float*)d_in[5];
    const float* bk    = (const float*)d_in[6];
    const float* wv    = (const float*)d_in[7];
    const float* bv    = (const float*)d_in[8];
    const float* w_out = (const float*)d_in[9];
    const float* b_out = (const float*)d_in[10];
    const float* gamma = (const float*)d_in[11];
    const float* ln_w  = (const float*)d_in[12];
    const float* ln_b  = (const float*)d_in[13];
    float* out = (float*)d_out;

    cudaFuncSetAttribute(k_conv3x3, cudaFuncAttributeMaxDynamicSharedMemorySize, CONV_SMEM);
    cudaFuncSetAttribute(k_attn,    cudaFuncAttributeMaxDynamicSharedMemorySize, ATTN_SMEM);

    k_inproj<<<dim3(64, BATCH), 256>>>(x, w_in, b_in);
    k_conv3x3<<<dim3(4, 4, BATCH*3), 256, CONV_SMEM>>>(wq, bq, wk, bk, wv, bv);
    k_attn<<<dim3(64, BATCH), 256, ATTN_SMEM>>>();
    k_outproj_ln<<<dim3(64, BATCH), 256>>>(x, w_out, b_out, gamma, ln_w, ln_b, out);
}